// round 15
// baseline (speedup 1.0000x reference)
#include <cuda_runtime.h>
#include <cuda_bf16.h>
#include <cstdint>

// Problem constants
#define BATCH 2
#define SEQ   2048
#define HID   1024
#define HEADS 16
#define HDIM  64
#define QKVW  (3*HID)      // 3072
#define MROWS (BATCH*SEQ)  // 4096
#define KDIM  1024

// Scratch (device globals — no allocation allowed)
__device__ float g_qkv[(size_t)MROWS * QKVW];   // [B,S,3,H,D] (post-rope q,k)
__device__ float g_att[(size_t)MROWS * HID];    // [B,S,H,D] (tf32-rounded)
__device__ float g_hsr[(size_t)MROWS * KDIM];   // hs, tf32-rounded
__device__ float g_wqT[(size_t)QKVW * KDIM];    // Wqkv^T [N][K]
__device__ float g_woT[(size_t)HID * KDIM];     // Wo^T   [N][K]

// ---------------------------------------------------------------------------
// PTX helpers
// ---------------------------------------------------------------------------
__device__ __forceinline__ float tf32r(float x) {
    uint32_t u;
    asm("cvt.rna.tf32.f32 %0, %1;" : "=r"(u) : "f"(x));
    return __uint_as_float(u);
}
__device__ __forceinline__ uint32_t s2u(const void* p) {
    uint32_t a;
    asm("{ .reg .u64 t; cvta.to.shared.u64 t, %1; cvt.u32.u64 %0, t; }"
        : "=r"(a) : "l"(p));
    return a;
}
__device__ __forceinline__ void mma_tf32(float* d, const uint32_t* a, const uint32_t* b) {
    asm volatile(
        "mma.sync.aligned.m16n8k8.row.col.f32.tf32.tf32.f32 "
        "{%0,%1,%2,%3}, {%4,%5,%6,%7}, {%8,%9}, {%0,%1,%2,%3};\n"
        : "+f"(d[0]), "+f"(d[1]), "+f"(d[2]), "+f"(d[3])
        : "r"(a[0]), "r"(a[1]), "r"(a[2]), "r"(a[3]),
          "r"(b[0]), "r"(b[1]));
}
__device__ __forceinline__ void cp_async16(uint32_t saddr, const void* g) {
    asm volatile("cp.async.cg.shared.global [%0], [%1], 16;" :: "r"(saddr), "l"(g));
}
__device__ __forceinline__ void cp_commit() {
    asm volatile("cp.async.commit_group;" ::: "memory");
}
__device__ __forceinline__ void cp_wait1() {
    asm volatile("cp.async.wait_group 1;" ::: "memory");
}
__device__ __forceinline__ void ldsm_x4(uint32_t* r, uint32_t addr) {
    asm volatile("ldmatrix.sync.aligned.m8n8.x4.shared.b16 {%0,%1,%2,%3}, [%4];"
                 : "=r"(r[0]), "=r"(r[1]), "=r"(r[2]), "=r"(r[3]) : "r"(addr));
}

// ---------------------------------------------------------------------------
// Pre-pass kernels: tf32 rounding / transpose+round
// ---------------------------------------------------------------------------
__global__ void round_tf32(const float* __restrict__ x, float* __restrict__ y, int n)
{
    int i = (blockIdx.x * blockDim.x + threadIdx.x) * 4;
    if (i >= n) return;
    float4 v = *(const float4*)(x + i);
    v.x = tf32r(v.x); v.y = tf32r(v.y); v.z = tf32r(v.z); v.w = tf32r(v.w);
    *(float4*)(y + i) = v;
}

__global__ void transpose_round(const float* __restrict__ W, float* __restrict__ T,
                                int K, int N)
{
    __shared__ float t[32][33];
    int n0 = blockIdx.x * 32, k0 = blockIdx.y * 32;
    int tx = threadIdx.x, ty = threadIdx.y;
#pragma unroll
    for (int i = 0; i < 4; i++)
        t[ty + 8 * i][tx] = W[(size_t)(k0 + ty + 8 * i) * N + n0 + tx];
    __syncthreads();
#pragma unroll
    for (int i = 0; i < 4; i++)
        T[(size_t)(n0 + ty + 8 * i) * K + k0 + tx] = tf32r(t[tx][ty + 8 * i]);
}

// ---------------------------------------------------------------------------
// tf32 GEMM, cp.async + ldmatrix + mma.
// 128 threads (4 warps, 2m x 2n grid), WARP TILE 64x64 (full 128x128 CTA tile:
// 2*64 m  x  2*64 n). Fragment smem traffic: 4*(64+64)*32*4 = 64KB reads +
// 32KB writes per chunk = 0.75 of the 1024-cyc tensor floor (was 1.0).
//   C[M,N] = A[M,1024] @ Bt[N,1024]^T + bias[N]   (+ optional fused RoPE)
// ---------------------------------------------------------------------------
#define GSMEM (3 * 32768)

__global__ __launch_bounds__(128) void gemm_tf32_cp(
    const float* __restrict__ A, const float* __restrict__ Bt,
    const float* __restrict__ bias, float* __restrict__ C, int N,
    const float* __restrict__ rope)
{
    extern __shared__ char smc[];
    const uint32_t sbase = s2u(smc);
    const int tid = threadIdx.x, lane = tid & 31, wid = tid >> 5;
    const int wm = wid >> 1, wn = wid & 1;       // 2x2 warp grid
    const int m0 = blockIdx.y * 128, n0 = blockIdx.x * 128;

    float acc[4][8][4];                          // [mt][nt][frag]
#pragma unroll
    for (int i = 0; i < 4; i++)
#pragma unroll
        for (int j = 0; j < 8; j++)
#pragma unroll
            for (int c = 0; c < 4; c++) acc[i][j][c] = 0.0f;

#define ISSUE(ck, st)                                                         \
    {                                                                         \
        const float* pA_ = A + (size_t)m0 * KDIM + (ck) * 32;                 \
        const float* pB_ = Bt + (size_t)n0 * KDIM + (ck) * 32;                \
        uint32_t sa_ = sbase + (uint32_t)(st) * 32768u;                       \
        _Pragma("unroll")                                                     \
        for (int i_ = 0; i_ < 8; i_++) {                                      \
            int u_ = tid + i_ * 128;                                          \
            int row_ = u_ >> 3, c_ = u_ & 7;                                  \
            uint32_t off_ = row_ * 128 + ((c_ ^ (row_ & 7)) << 4);            \
            cp_async16(sa_ + off_, pA_ + (size_t)row_ * KDIM + c_ * 4);       \
            cp_async16(sa_ + 16384u + off_, pB_ + (size_t)row_ * KDIM + c_ * 4); \
        }                                                                     \
    }

    ISSUE(0, 0); cp_commit();
    ISSUE(1, 1); cp_commit();

    const int g = lane >> 3, l7 = lane & 7;
    int st = 0;
    for (int ck = 0; ck < KDIM / 32; ck++) {
        cp_wait1();
        __syncthreads();
        int nst = st + 2; if (nst >= 3) nst -= 3;
        if (ck + 2 < KDIM / 32) ISSUE(ck + 2, nst);
        cp_commit();

        uint32_t sa = sbase + (uint32_t)st * 32768u;
        uint32_t sb2 = sa + 16384u;
#pragma unroll
        for (int kt = 0; kt < 4; kt++) {
            uint32_t af[4][4];
#pragma unroll
            for (int mt = 0; mt < 4; mt++) {
                int row = wm * 64 + mt * 16 + ((g & 1) << 3) + l7;
                int c = 2 * kt + (g >> 1);
                ldsm_x4(af[mt], sa + row * 128 + ((c ^ l7) << 4));
            }
            uint32_t bf[8][2];
#pragma unroll
            for (int p = 0; p < 4; p++) {
                int row = wn * 64 + p * 16 + ((g >> 1) << 3) + l7;
                int c = 2 * kt + (g & 1);
                uint32_t r4[4];
                ldsm_x4(r4, sb2 + row * 128 + ((c ^ l7) << 4));
                bf[2 * p][0] = r4[0]; bf[2 * p][1] = r4[1];
                bf[2 * p + 1][0] = r4[2]; bf[2 * p + 1][1] = r4[3];
            }
#pragma unroll
            for (int mt = 0; mt < 4; mt++)
#pragma unroll
                for (int nt = 0; nt < 8; nt++)
                    mma_tf32(acc[mt][nt], af[mt], bf[nt]);
        }
        st++; if (st == 3) st = 0;
    }
#undef ISSUE

    // ---- epilogue: bias (+ fused RoPE on q,k columns) + store ----
    const int gr = lane >> 2;
    const int gc = (lane & 3) << 1;
#pragma unroll
    for (int nt = 0; nt < 8; nt++) {
        int col = n0 + wn * 64 + nt * 8 + gc;
        float2 bb = *(const float2*)(bias + col);
        const bool do_rope = (rope != nullptr) && (col < 2 * HID);
        const int d2 = (col & 63) >> 1;
#pragma unroll
        for (int mt = 0; mt < 4; mt++) {
            int row = m0 + wm * 64 + mt * 16 + gr;
            float2 v0, v1;
            v0.x = acc[mt][nt][0] + bb.x;
            v0.y = acc[mt][nt][1] + bb.y;
            v1.x = acc[mt][nt][2] + bb.x;
            v1.y = acc[mt][nt][3] + bb.y;
            if (do_rope) {
                int p0 = row & 255;
                int p1 = (row + 8) & 255;
                float2 cs0 = *(const float2*)(rope + (p0 * 32 + d2) * 2);
                float2 cs1 = *(const float2*)(rope + (p1 * 32 + d2) * 2);
                float t0 = v0.x * cs0.x - v0.y * cs0.y;
                v0.y = v0.y * cs0.x + v0.x * cs0.y;
                v0.x = t0;
                float t1 = v1.x * cs1.x - v1.y * cs1.y;
                v1.y = v1.y * cs1.x + v1.x * cs1.y;
                v1.x = t1;
            }
            *(float2*)(C + (size_t)row * N + col)       = v0;
            *(float2*)(C + (size_t)(row + 8) * N + col) = v1;
        }
    }
}

// ---------------------------------------------------------------------------
// Banded attention with 3xTF32 mma (round-12 version, unchanged).
// ---------------------------------------------------------------------------
#define QT   64
#define SCW  321
#define ATTN_SMEM ((4*4096 + 64*SCW + 256) * (int)sizeof(float))

__global__ __launch_bounds__(256) void attn_mma(
    const float* __restrict__ qkv, float* __restrict__ att)
{
    extern __shared__ float smf[];
    float* Qh = smf;
    float* Ql = smf + 4096;
    float* Kh = smf + 8192;
    float* Kl = smf + 12288;
    float* sc = smf + 16384;
    float* red = sc + 64 * SCW;

    const int tid  = threadIdx.x;
    const int lane = tid & 31, wid = tid >> 5;
    const int wm = wid >> 1, wn = wid & 1;
    const int q0 = blockIdx.x * QT;
    const int h  = blockIdx.y, b = blockIdx.z;
    const int kb = q0 - 128;
    const int gr = lane >> 2, gc = (lane & 3) << 1;

    {
        const float* qbase = qkv + ((size_t)(b * SEQ + q0)) * QKVW + h * HDIM;
#pragma unroll
        for (int i = 0; i < 4; i++) {
            int idx = tid + i * 256;
            int row = idx >> 4, c4 = (idx & 15) << 2;
            float4 v = *(const float4*)(qbase + (size_t)row * QKVW + c4);
            float vv[4] = {v.x, v.y, v.z, v.w};
#pragma unroll
            for (int j = 0; j < 4; j++) {
                int k = c4 + j;
                int tm = row >> 4, tk = k >> 3, r = row & 15;
                int ln = ((r & 7) << 2) | (k & 3);
                int rg = (((k >> 2) & 1) << 1) | (r >> 3);
                int slot = ((tm * 8 + tk) << 7) + ((ln ^ tk) << 2) + rg;
                float hi = tf32r(vv[j]);
                Qh[slot] = hi;
                Ql[slot] = tf32r(vv[j] - hi);
            }
        }
    }

    for (int t = 0; t < 5; t++) {
        __syncthreads();
#pragma unroll
        for (int i = 0; i < 4; i++) {
            int idx = tid + i * 256;
            int key = idx >> 4, c4 = (idx & 15) << 2;
            int kj = kb + t * 64 + key;
            float4 v = make_float4(0.f, 0.f, 0.f, 0.f);
            if (kj >= 0 && kj < SEQ)
                v = *(const float4*)(qkv + ((size_t)(b * SEQ + kj)) * QKVW + HID + h * HDIM + c4);
            float vv[4] = {v.x, v.y, v.z, v.w};
#pragma unroll
            for (int j = 0; j < 4; j++) {
                int d = c4 + j;
                int kt = d >> 3, tn = key >> 3;
                int ln = ((key & 7) << 2) | (d & 3);
                int rg = (d >> 2) & 1;
                int slot = ((kt * 8 + tn) << 6) + ((ln ^ (tn & 7)) << 1) + rg;
                float hi = tf32r(vv[j]);
                Kh[slot] = hi;
                Kl[slot] = tf32r(vv[j] - hi);
            }
        }
        __syncthreads();

        float c[4][4];
#pragma unroll
        for (int nt = 0; nt < 4; nt++)
#pragma unroll
            for (int e = 0; e < 4; e++) c[nt][e] = 0.0f;

#pragma unroll
        for (int kt = 0; kt < 8; kt++) {
            uint4 ah = ((const uint4*)Qh)[((wm * 8 + kt) << 5) + (lane ^ kt)];
            uint4 al = ((const uint4*)Ql)[((wm * 8 + kt) << 5) + (lane ^ kt)];
#pragma unroll
            for (int nt = 0; nt < 4; nt++) {
                int tn = wn * 4 + nt;
                uint2 bh = ((const uint2*)Kh)[((kt * 8 + tn) << 5) + (lane ^ (tn & 7))];
                uint2 bl = ((const uint2*)Kl)[((kt * 8 + tn) << 5) + (lane ^ (tn & 7))];
                mma_tf32(c[nt], (const uint32_t*)&ah, (const uint32_t*)&bh);
                mma_tf32(c[nt], (const uint32_t*)&ah, (const uint32_t*)&bl);
                mma_tf32(c[nt], (const uint32_t*)&al, (const uint32_t*)&bh);
            }
        }
#pragma unroll
        for (int nt = 0; nt < 4; nt++) {
#pragma unroll
            for (int half = 0; half < 2; half++) {
                int row = wm * 16 + gr + half * 8;
                int qi = q0 + row;
#pragma unroll
                for (int e = 0; e < 2; e++) {
                    int col = wn * 32 + nt * 8 + gc + e;
                    int kj = kb + t * 64 + col;
                    int rel = qi - kj;
                    bool valid = (kj >= 0) && (kj < SEQ) && (rel <= 128) && (rel >= -128);
                    sc[row * SCW + t * 64 + col] = valid ? c[nt][half * 2 + e] * 0.125f : -1e30f;
                }
            }
        }
    }
    __syncthreads();

    {
        const int part = tid >> 6;
        const int row  = tid & 63;
        const int c0 = part * 80;
        float mx = -1e30f;
        for (int c = c0; c < c0 + 80; c++) mx = fmaxf(mx, sc[row * SCW + c]);
        red[part * 64 + row] = mx;
        __syncthreads();
        float m = fmaxf(fmaxf(red[row], red[64 + row]),
                        fmaxf(red[128 + row], red[192 + row]));
        __syncthreads();
        float sumv = 0.0f;
        for (int c = c0; c < c0 + 80; c++) {
            float e = __expf(sc[row * SCW + c] - m);
            sc[row * SCW + c] = e;
            sumv += e;
        }
        red[part * 64 + row] = sumv;
    }

    float o[4][4];
#pragma unroll
    for (int nt = 0; nt < 4; nt++)
#pragma unroll
        for (int e = 0; e < 4; e++) o[nt][e] = 0.0f;

    for (int t = 0; t < 5; t++) {
        __syncthreads();
#pragma unroll
        for (int i = 0; i < 4; i++) {
            int idx = tid + i * 256;
            int key = idx >> 4, c4 = (idx & 15) << 2;
            int kj = kb + t * 64 + key;
            float4 v = make_float4(0.f, 0.f, 0.f, 0.f);
            if (kj >= 0 && kj < SEQ)
                v = *(const float4*)(qkv + ((size_t)(b * SEQ + kj)) * QKVW + 2 * HID + h * HDIM + c4);
            float vv[4] = {v.x, v.y, v.z, v.w};
#pragma unroll
            for (int j = 0; j < 4; j++) {
                int d = c4 + j;
                int kt = key >> 3, tn = d >> 3;
                int ln = ((d & 7) << 2) | (key & 3);
                int rg = (key >> 2) & 1;
                int slot = ((kt * 8 + tn) << 6) + ((ln ^ (tn & 7)) << 1) + rg;
                float hi = tf32r(vv[j]);
                Kh[slot] = hi;
                Kl[slot] = tf32r(vv[j] - hi);
            }
        }
        __syncthreads();

#pragma unroll
        for (int kt = 0; kt < 8; kt++) {
            int kk = t * 64 + kt * 8 + (lane & 3);
            int r0 = wm * 16 + gr;
            float p00 = sc[r0 * SCW + kk];
            float p10 = sc[(r0 + 8) * SCW + kk];
            float p01 = sc[r0 * SCW + kk + 4];
            float p11 = sc[(r0 + 8) * SCW + kk + 4];
            float ah[4], al[4];
            ah[0] = tf32r(p00); al[0] = tf32r(p00 - ah[0]);
            ah[1] = tf32r(p10); al[1] = tf32r(p10 - ah[1]);
            ah[2] = tf32r(p01); al[2] = tf32r(p01 - ah[2]);
            ah[3] = tf32r(p11); al[3] = tf32r(p11 - ah[3]);
#pragma unroll
            for (int nt = 0; nt < 4; nt++) {
                int tn = wn * 4 + nt;
                uint2 bh = ((const uint2*)Kh)[((kt * 8 + tn) << 5) + (lane ^ (tn & 7))];
                uint2 bl = ((const uint2*)Kl)[((kt * 8 + tn) << 5) + (lane ^ (tn & 7))];
                mma_tf32(o[nt], (const uint32_t*)ah, (const uint32_t*)&bh);
                mma_tf32(o[nt], (const uint32_t*)ah, (const uint32_t*)&bl);
                mma_tf32(o[nt], (const uint32_t*)al, (const uint32_t*)&bh);
            }
        }
    }

    // epilogue: divide by row sums, store TF32-ROUNDED to att [B,S,H,D]
#pragma unroll
    for (int half = 0; half < 2; half++) {
        int row = wm * 16 + gr + half * 8;
        float rs = red[row] + red[64 + row] + red[128 + row] + red[192 + row];
        float inv = 1.0f / rs;
        int qi = q0 + row;
        float* obase = att + ((size_t)((b * SEQ + qi) * HEADS + h)) * HDIM;
#pragma unroll
        for (int nt = 0; nt < 4; nt++) {
            int col = wn * 32 + nt * 8 + gc;
            float2 v;
            v.x = tf32r(o[nt][half * 2 + 0] * inv);
            v.y = tf32r(o[nt][half * 2 + 1] * inv);
            *(float2*)(obase + col) = v;
        }
    }
}

// ---------------------------------------------------------------------------
// Launch
// ---------------------------------------------------------------------------
extern "C" void kernel_launch(void* const* d_in, const int* in_sizes, int n_in,
                              void* d_out, int out_size)
{
    const float* hs   = (const float*)d_in[0];
    const float* wqkv = (const float*)d_in[1];
    const float* bqkv = (const float*)d_in[2];
    const float* wo   = (const float*)d_in[3];
    const float* bo   = (const float*)d_in[4];
    const float* rope = (const float*)d_in[5];
    float* out = (float*)d_out;

    float *qkv, *att, *hsr, *wqT, *woT;
    cudaGetSymbolAddress((void**)&qkv, g_qkv);
    cudaGetSymbolAddress((void**)&att, g_att);
    cudaGetSymbolAddress((void**)&hsr, g_hsr);
    cudaGetSymbolAddress((void**)&wqT, g_wqT);
    cudaGetSymbolAddress((void**)&woT, g_woT);

    cudaFuncSetAttribute(gemm_tf32_cp,
                         cudaFuncAttributeMaxDynamicSharedMemorySize, GSMEM);
    cudaFuncSetAttribute(attn_mma,
                         cudaFuncAttributeMaxDynamicSharedMemorySize, ATTN_SMEM);

    // 0) Pre-pass: tf32-round hs; transpose+round weights to [N][K]
    round_tf32<<<(MROWS * KDIM) / 1024, 256>>>(hs, hsr, MROWS * KDIM);
    transpose_round<<<dim3(QKVW / 32, KDIM / 32), dim3(32, 8)>>>(wqkv, wqT, KDIM, QKVW);
    transpose_round<<<dim3(HID / 32, KDIM / 32), dim3(32, 8)>>>(wo, woT, KDIM, HID);

    // 1) QKV projection with FUSED RoPE epilogue (128-thread CTAs, 64x64 warp tile)
    gemm_tf32_cp<<<dim3(QKVW / 128, MROWS / 128), 128, GSMEM>>>(
        hsr, wqT, bqkv, qkv, QKVW, rope);

    // 2) Banded attention (3xTF32 mma)
    attn_mma<<<dim3(SEQ / QT, HEADS, BATCH), 256, ATTN_SMEM>>>(qkv, att);

    // 3) Output projection (no rope)
    gemm_tf32_cp<<<dim3(HID / 128, MROWS / 128), 128, GSMEM>>>(
        att, woT, bo, out, HID, nullptr);
}

// round 16
// speedup vs baseline: 1.0399x; 1.0399x over previous
#include <cuda_runtime.h>
#include <cuda_bf16.h>
#include <cstdint>

// Problem constants
#define BATCH 2
#define SEQ   2048
#define HID   1024
#define HEADS 16
#define HDIM  64
#define QKVW  (3*HID)      // 3072
#define MROWS (BATCH*SEQ)  // 4096
#define KDIM  1024
#define NHB   (BATCH*HEADS)   // 32
#define NTIL  36              // (2048 + 2*128)/64 storage key tiles

// Scratch (device globals — no allocation allowed)
__device__ float g_qkv[(size_t)MROWS * QKVW];   // [B,S,3,H,D] (post-rope q,k)
__device__ float g_att[(size_t)MROWS * HID];    // [B,S,H,D] (tf32-rounded)
__device__ float g_hsr[(size_t)MROWS * KDIM];   // hs, tf32-rounded
__device__ float g_wqT[(size_t)QKVW * KDIM];    // Wqkv^T [N][K]
__device__ float g_woT[(size_t)HID * KDIM];     // Wo^T   [N][K]
// pre-split K/V fragment tiles: [hb][tile][4096]
__device__ float g_kfh[(size_t)NHB * NTIL * 4096];
__device__ float g_kfl[(size_t)NHB * NTIL * 4096];
__device__ float g_vfh[(size_t)NHB * NTIL * 4096];
__device__ float g_vfl[(size_t)NHB * NTIL * 4096];

// ---------------------------------------------------------------------------
// PTX helpers
// ---------------------------------------------------------------------------
__device__ __forceinline__ float tf32r(float x) {
    uint32_t u;
    asm("cvt.rna.tf32.f32 %0, %1;" : "=r"(u) : "f"(x));
    return __uint_as_float(u);
}
__device__ __forceinline__ uint32_t s2u(const void* p) {
    uint32_t a;
    asm("{ .reg .u64 t; cvta.to.shared.u64 t, %1; cvt.u32.u64 %0, t; }"
        : "=r"(a) : "l"(p));
    return a;
}
__device__ __forceinline__ void mma_tf32(float* d, const uint32_t* a, const uint32_t* b) {
    asm volatile(
        "mma.sync.aligned.m16n8k8.row.col.f32.tf32.tf32.f32 "
        "{%0,%1,%2,%3}, {%4,%5,%6,%7}, {%8,%9}, {%0,%1,%2,%3};\n"
        : "+f"(d[0]), "+f"(d[1]), "+f"(d[2]), "+f"(d[3])
        : "r"(a[0]), "r"(a[1]), "r"(a[2]), "r"(a[3]),
          "r"(b[0]), "r"(b[1]));
}
__device__ __forceinline__ void cp_async16(uint32_t saddr, const void* g) {
    asm volatile("cp.async.cg.shared.global [%0], [%1], 16;" :: "r"(saddr), "l"(g));
}
__device__ __forceinline__ void cp_commit() {
    asm volatile("cp.async.commit_group;" ::: "memory");
}
__device__ __forceinline__ void cp_wait1() {
    asm volatile("cp.async.wait_group 1;" ::: "memory");
}
__device__ __forceinline__ void ldsm_x4(uint32_t* r, uint32_t addr) {
    asm volatile("ldmatrix.sync.aligned.m8n8.x4.shared.b16 {%0,%1,%2,%3}, [%4];"
                 : "=r"(r[0]), "=r"(r[1]), "=r"(r[2]), "=r"(r[3]) : "r"(addr));
}

// ---------------------------------------------------------------------------
// Pre-pass kernels: tf32 rounding / transpose+round
// ---------------------------------------------------------------------------
__global__ void round_tf32(const float* __restrict__ x, float* __restrict__ y, int n)
{
    int i = (blockIdx.x * blockDim.x + threadIdx.x) * 4;
    if (i >= n) return;
    float4 v = *(const float4*)(x + i);
    v.x = tf32r(v.x); v.y = tf32r(v.y); v.z = tf32r(v.z); v.w = tf32r(v.w);
    *(float4*)(y + i) = v;
}

__global__ void transpose_round(const float* __restrict__ W, float* __restrict__ T,
                                int K, int N)
{
    __shared__ float t[32][33];
    int n0 = blockIdx.x * 32, k0 = blockIdx.y * 32;
    int tx = threadIdx.x, ty = threadIdx.y;
#pragma unroll
    for (int i = 0; i < 4; i++)
        t[ty + 8 * i][tx] = W[(size_t)(k0 + ty + 8 * i) * N + n0 + tx];
    __syncthreads();
#pragma unroll
    for (int i = 0; i < 4; i++)
        T[(size_t)(n0 + ty + 8 * i) * K + k0 + tx] = tf32r(t[tx][ty + 8 * i]);
}

// ---------------------------------------------------------------------------
// K/V fragment pre-split: one block per (storage tile, hb).
// Computes the EXACT same hi/lo fragment-layout images the attention kernel
// used to build in-kernel, dumps them linearly to global.
// Storage tile `tile` covers keys kj = tile*64 - 128 .. +63 (OOB -> zeros).
// ---------------------------------------------------------------------------
__global__ __launch_bounds__(256) void kv_frag_split(
    const float* __restrict__ qkv,
    float* __restrict__ kfh, float* __restrict__ kfl,
    float* __restrict__ vfh, float* __restrict__ vfl)
{
    __shared__ float Fh[4096], Fl[4096];
    const int tile = blockIdx.x;          // 0..35
    const int hb = blockIdx.y;
    const int b = hb >> 4, h = hb & 15;
    const int tid = threadIdx.x;
    const size_t base = ((size_t)hb * NTIL + tile) * 4096;

    // ---- K: B-layout with k=d, n=key ----
#pragma unroll
    for (int i = 0; i < 4; i++) {
        int idx = tid + i * 256;
        int key = idx >> 4, c4 = (idx & 15) << 2;
        int kj = tile * 64 + key - 128;
        float4 v = make_float4(0.f, 0.f, 0.f, 0.f);
        if (kj >= 0 && kj < SEQ)
            v = *(const float4*)(qkv + ((size_t)(b * SEQ + kj)) * QKVW + HID + h * HDIM + c4);
        float vv[4] = {v.x, v.y, v.z, v.w};
#pragma unroll
        for (int j = 0; j < 4; j++) {
            int d = c4 + j;
            int kt = d >> 3, tn = key >> 3;
            int ln = ((key & 7) << 2) | (d & 3);
            int rg = (d >> 2) & 1;
            int slot = ((kt * 8 + tn) << 6) + ((ln ^ (tn & 7)) << 1) + rg;
            float hi = tf32r(vv[j]);
            Fh[slot] = hi;
            Fl[slot] = tf32r(vv[j] - hi);
        }
    }
    __syncthreads();
#pragma unroll
    for (int i = 0; i < 4; i++) {
        int idx = tid + i * 256;
        ((float4*)(kfh + base))[idx] = ((const float4*)Fh)[idx];
        ((float4*)(kfl + base))[idx] = ((const float4*)Fl)[idx];
    }
    __syncthreads();

    // ---- V: B-layout with k=key, n=d ----
#pragma unroll
    for (int i = 0; i < 4; i++) {
        int idx = tid + i * 256;
        int key = idx >> 4, c4 = (idx & 15) << 2;
        int kj = tile * 64 + key - 128;
        float4 v = make_float4(0.f, 0.f, 0.f, 0.f);
        if (kj >= 0 && kj < SEQ)
            v = *(const float4*)(qkv + ((size_t)(b * SEQ + kj)) * QKVW + 2 * HID + h * HDIM + c4);
        float vv[4] = {v.x, v.y, v.z, v.w};
#pragma unroll
        for (int j = 0; j < 4; j++) {
            int d = c4 + j;
            int kt = key >> 3, tn = d >> 3;
            int ln = ((d & 7) << 2) | (key & 3);
            int rg = (key >> 2) & 1;
            int slot = ((kt * 8 + tn) << 6) + ((ln ^ (tn & 7)) << 1) + rg;
            float hi = tf32r(vv[j]);
            Fh[slot] = hi;
            Fl[slot] = tf32r(vv[j] - hi);
        }
    }
    __syncthreads();
#pragma unroll
    for (int i = 0; i < 4; i++) {
        int idx = tid + i * 256;
        ((float4*)(vfh + base))[idx] = ((const float4*)Fh)[idx];
        ((float4*)(vfl + base))[idx] = ((const float4*)Fl)[idx];
    }
}

// ---------------------------------------------------------------------------
// tf32 GEMM, cp.async + ldmatrix + mma (round-12 config: 256 thr, 4m x 2n
// warps of 32x64, regs 128 — the known-good 147.8us configuration).
//   C[M,N] = A[M,1024] @ Bt[N,1024]^T + bias[N]   (+ optional fused RoPE)
// ---------------------------------------------------------------------------
#define GSMEM (3 * 32768)

__global__ __launch_bounds__(256, 2) void gemm_tf32_cp(
    const float* __restrict__ A, const float* __restrict__ Bt,
    const float* __restrict__ bias, float* __restrict__ C, int N,
    const float* __restrict__ rope)
{
    extern __shared__ char smc[];
    const uint32_t sbase = s2u(smc);
    const int tid = threadIdx.x, lane = tid & 31, wid = tid >> 5;
    const int wm = wid >> 1, wn = wid & 1;
    const int m0 = blockIdx.y * 128, n0 = blockIdx.x * 128;

    float acc[2][8][4];
#pragma unroll
    for (int i = 0; i < 2; i++)
#pragma unroll
        for (int j = 0; j < 8; j++)
#pragma unroll
            for (int c = 0; c < 4; c++) acc[i][j][c] = 0.0f;

#define ISSUE(ck, st)                                                         \
    {                                                                         \
        const float* pA_ = A + (size_t)m0 * KDIM + (ck) * 32;                 \
        const float* pB_ = Bt + (size_t)n0 * KDIM + (ck) * 32;                \
        uint32_t sa_ = sbase + (uint32_t)(st) * 32768u;                       \
        _Pragma("unroll")                                                     \
        for (int i_ = 0; i_ < 4; i_++) {                                      \
            int u_ = tid + i_ * 256;                                          \
            int row_ = u_ >> 3, c_ = u_ & 7;                                  \
            uint32_t off_ = row_ * 128 + ((c_ ^ (row_ & 7)) << 4);            \
            cp_async16(sa_ + off_, pA_ + (size_t)row_ * KDIM + c_ * 4);       \
            cp_async16(sa_ + 16384u + off_, pB_ + (size_t)row_ * KDIM + c_ * 4); \
        }                                                                     \
    }

    ISSUE(0, 0); cp_commit();
    ISSUE(1, 1); cp_commit();

    const int g = lane >> 3, l7 = lane & 7;
    int st = 0;
    for (int ck = 0; ck < KDIM / 32; ck++) {
        cp_wait1();
        __syncthreads();
        int nst = st + 2; if (nst >= 3) nst -= 3;
        if (ck + 2 < KDIM / 32) ISSUE(ck + 2, nst);
        cp_commit();

        uint32_t sa = sbase + (uint32_t)st * 32768u;
        uint32_t sb2 = sa + 16384u;
#pragma unroll
        for (int kt = 0; kt < 4; kt++) {
            uint32_t a[2][4];
#pragma unroll
            for (int mt = 0; mt < 2; mt++) {
                int row = wm * 32 + mt * 16 + ((g & 1) << 3) + l7;
                int c = 2 * kt + (g >> 1);
                ldsm_x4(a[mt], sa + row * 128 + ((c ^ l7) << 4));
            }
            uint32_t b[8][2];
#pragma unroll
            for (int p = 0; p < 4; p++) {
                int row = wn * 64 + p * 16 + ((g >> 1) << 3) + l7;
                int c = 2 * kt + (g & 1);
                uint32_t r4[4];
                ldsm_x4(r4, sb2 + row * 128 + ((c ^ l7) << 4));
                b[2 * p][0] = r4[0]; b[2 * p][1] = r4[1];
                b[2 * p + 1][0] = r4[2]; b[2 * p + 1][1] = r4[3];
            }
#pragma unroll
            for (int mt = 0; mt < 2; mt++)
#pragma unroll
                for (int nt = 0; nt < 8; nt++)
                    mma_tf32(acc[mt][nt], a[mt], b[nt]);
        }
        st++; if (st == 3) st = 0;
    }
#undef ISSUE

    // ---- epilogue: bias (+ fused RoPE on q,k columns) + store ----
    const int gr = lane >> 2;
    const int gc = (lane & 3) << 1;
#pragma unroll
    for (int nt = 0; nt < 8; nt++) {
        int col = n0 + wn * 64 + nt * 8 + gc;
        float2 bb = *(const float2*)(bias + col);
        const bool do_rope = (rope != nullptr) && (col < 2 * HID);
        const int d2 = (col & 63) >> 1;
#pragma unroll
        for (int mt = 0; mt < 2; mt++) {
            int row = m0 + wm * 32 + mt * 16 + gr;
            float2 v0, v1;
            v0.x = acc[mt][nt][0] + bb.x;
            v0.y = acc[mt][nt][1] + bb.y;
            v1.x = acc[mt][nt][2] + bb.x;
            v1.y = acc[mt][nt][3] + bb.y;
            if (do_rope) {
                int p0 = row & 255;
                int p1 = (row + 8) & 255;
                float2 cs0 = *(const float2*)(rope + (p0 * 32 + d2) * 2);
                float2 cs1 = *(const float2*)(rope + (p1 * 32 + d2) * 2);
                float t0 = v0.x * cs0.x - v0.y * cs0.y;
                v0.y = v0.y * cs0.x + v0.x * cs0.y;
                v0.x = t0;
                float t1 = v1.x * cs1.x - v1.y * cs1.y;
                v1.y = v1.y * cs1.x + v1.x * cs1.y;
                v1.x = t1;
            }
            *(float2*)(C + (size_t)row * N + col)       = v0;
            *(float2*)(C + (size_t)(row + 8) * N + col) = v1;
        }
    }
}

// ---------------------------------------------------------------------------
// Banded attention with 3xTF32 mma. K/V staging is now a pure vectorized
// copy from the pre-split fragment tiles (no cvt, no scatter, no predication).
// ---------------------------------------------------------------------------
#define QT   64
#define SCW  321
#define ATTN_SMEM ((4*4096 + 64*SCW + 256) * (int)sizeof(float))

__global__ __launch_bounds__(256) void attn_mma(
    const float* __restrict__ qkv,
    const float* __restrict__ kfh, const float* __restrict__ kfl,
    const float* __restrict__ vfh, const float* __restrict__ vfl,
    float* __restrict__ att)
{
    extern __shared__ float smf[];
    float* Qh = smf;
    float* Ql = smf + 4096;
    float* Kh = smf + 8192;
    float* Kl = smf + 12288;
    float* sc = smf + 16384;
    float* red = sc + 64 * SCW;

    const int tid  = threadIdx.x;
    const int lane = tid & 31, wid = tid >> 5;
    const int wm = wid >> 1, wn = wid & 1;
    const int q0 = blockIdx.x * QT;
    const int h  = blockIdx.y, b = blockIdx.z;
    const int hb = b * HEADS + h;
    const int kb = q0 - 128;
    const int gr = lane >> 2, gc = (lane & 3) << 1;
    const size_t tile0 = (size_t)hb * NTIL + (q0 >> 6);   // storage tile of t=0

    // ---- stage Q (in-kernel split, used once) ----
    {
        const float* qbase = qkv + ((size_t)(b * SEQ + q0)) * QKVW + h * HDIM;
#pragma unroll
        for (int i = 0; i < 4; i++) {
            int idx = tid + i * 256;
            int row = idx >> 4, c4 = (idx & 15) << 2;
            float4 v = *(const float4*)(qbase + (size_t)row * QKVW + c4);
            float vv[4] = {v.x, v.y, v.z, v.w};
#pragma unroll
            for (int j = 0; j < 4; j++) {
                int k = c4 + j;
                int tm = row >> 4, tk = k >> 3, r = row & 15;
                int ln = ((r & 7) << 2) | (k & 3);
                int rg = (((k >> 2) & 1) << 1) | (r >> 3);
                int slot = ((tm * 8 + tk) << 7) + ((ln ^ tk) << 2) + rg;
                float hi = tf32r(vv[j]);
                Qh[slot] = hi;
                Ql[slot] = tf32r(vv[j] - hi);
            }
        }
    }

    // ---- phase 1: scores ----
    for (int t = 0; t < 5; t++) {
        __syncthreads();
        {
            const float4* sh = (const float4*)(kfh + (tile0 + t) * 4096);
            const float4* sl = (const float4*)(kfl + (tile0 + t) * 4096);
#pragma unroll
            for (int i = 0; i < 4; i++) {
                int idx = tid + i * 256;
                ((float4*)Kh)[idx] = sh[idx];
                ((float4*)Kl)[idx] = sl[idx];
            }
        }
        __syncthreads();

        float c[4][4];
#pragma unroll
        for (int nt = 0; nt < 4; nt++)
#pragma unroll
            for (int e = 0; e < 4; e++) c[nt][e] = 0.0f;

#pragma unroll
        for (int kt = 0; kt < 8; kt++) {
            uint4 ah = ((const uint4*)Qh)[((wm * 8 + kt) << 5) + (lane ^ kt)];
            uint4 al = ((const uint4*)Ql)[((wm * 8 + kt) << 5) + (lane ^ kt)];
#pragma unroll
            for (int nt = 0; nt < 4; nt++) {
                int tn = wn * 4 + nt;
                uint2 bh = ((const uint2*)Kh)[((kt * 8 + tn) << 5) + (lane ^ (tn & 7))];
                uint2 bl = ((const uint2*)Kl)[((kt * 8 + tn) << 5) + (lane ^ (tn & 7))];
                mma_tf32(c[nt], (const uint32_t*)&ah, (const uint32_t*)&bh);
                mma_tf32(c[nt], (const uint32_t*)&ah, (const uint32_t*)&bl);
                mma_tf32(c[nt], (const uint32_t*)&al, (const uint32_t*)&bh);
            }
        }
#pragma unroll
        for (int nt = 0; nt < 4; nt++) {
#pragma unroll
            for (int half = 0; half < 2; half++) {
                int row = wm * 16 + gr + half * 8;
                int qi = q0 + row;
#pragma unroll
                for (int e = 0; e < 2; e++) {
                    int col = wn * 32 + nt * 8 + gc + e;
                    int kj = kb + t * 64 + col;
                    int rel = qi - kj;
                    bool valid = (kj >= 0) && (kj < SEQ) && (rel <= 128) && (rel >= -128);
                    sc[row * SCW + t * 64 + col] = valid ? c[nt][half * 2 + e] * 0.125f : -1e30f;
                }
            }
        }
    }
    __syncthreads();

    // ---- phase 2: exact softmax over 320 cols ----
    {
        const int part = tid >> 6;
        const int row  = tid & 63;
        const int c0 = part * 80;
        float mx = -1e30f;
        for (int c = c0; c < c0 + 80; c++) mx = fmaxf(mx, sc[row * SCW + c]);
        red[part * 64 + row] = mx;
        __syncthreads();
        float m = fmaxf(fmaxf(red[row], red[64 + row]),
                        fmaxf(red[128 + row], red[192 + row]));
        __syncthreads();
        float sumv = 0.0f;
        for (int c = c0; c < c0 + 80; c++) {
            float e = __expf(sc[row * SCW + c] - m);
            sc[row * SCW + c] = e;
            sumv += e;
        }
        red[part * 64 + row] = sumv;
    }

    // ---- phase 3: PV ----
    float o[4][4];
#pragma unroll
    for (int nt = 0; nt < 4; nt++)
#pragma unroll
        for (int e = 0; e < 4; e++) o[nt][e] = 0.0f;

    for (int t = 0; t < 5; t++) {
        __syncthreads();
        {
            const float4* sh = (const float4*)(vfh + (tile0 + t) * 4096);
            const float4* sl = (const float4*)(vfl + (tile0 + t) * 4096);
#pragma unroll
            for (int i = 0; i < 4; i++) {
                int idx = tid + i * 256;
                ((float4*)Kh)[idx] = sh[idx];
                ((float4*)Kl)[idx] = sl[idx];
            }
        }
        __syncthreads();

#pragma unroll
        for (int kt = 0; kt < 8; kt++) {
            int kk = t * 64 + kt * 8 + (lane & 3);
            int r0 = wm * 16 + gr;
            float p00 = sc[r0 * SCW + kk];
            float p10 = sc[(r0 + 8) * SCW + kk];
            float p01 = sc[r0 * SCW + kk + 4];
            float p11 = sc[(r0 + 8) * SCW + kk + 4];
            float ah[4], al[4];
            ah[0] = tf32r(p00); al[0] = tf32r(p00 - ah[0]);
            ah[1] = tf32r(p10); al[1] = tf32r(p10 - ah[1]);
            ah[2] = tf32r(p01); al[2] = tf32r(p01 - ah[2]);
            ah[3] = tf32r(p11); al[3] = tf32r(p11 - ah[3]);
#pragma unroll
            for (int nt = 0; nt < 4; nt++) {
                int tn = wn * 4 + nt;
                uint2 bh = ((const uint2*)Kh)[((kt * 8 + tn) << 5) + (lane ^ (tn & 7))];
                uint2 bl = ((const uint2*)Kl)[((kt * 8 + tn) << 5) + (lane ^ (tn & 7))];
                mma_tf32(o[nt], (const uint32_t*)ah, (const uint32_t*)&bh);
                mma_tf32(o[nt], (const uint32_t*)ah, (const uint32_t*)&bl);
                mma_tf32(o[nt], (const uint32_t*)al, (const uint32_t*)&bh);
            }
        }
    }

    // ---- epilogue: divide by row sums, store TF32-ROUNDED to att ----
#pragma unroll
    for (int half = 0; half < 2; half++) {
        int row = wm * 16 + gr + half * 8;
        float rs = red[row] + red[64 + row] + red[128 + row] + red[192 + row];
        float inv = 1.0f / rs;
        int qi = q0 + row;
        float* obase = att + ((size_t)((b * SEQ + qi) * HEADS + h)) * HDIM;
#pragma unroll
        for (int nt = 0; nt < 4; nt++) {
            int col = wn * 32 + nt * 8 + gc;
            float2 v;
            v.x = tf32r(o[nt][half * 2 + 0] * inv);
            v.y = tf32r(o[nt][half * 2 + 1] * inv);
            *(float2*)(obase + col) = v;
        }
    }
}

// ---------------------------------------------------------------------------
// Launch
// ---------------------------------------------------------------------------
extern "C" void kernel_launch(void* const* d_in, const int* in_sizes, int n_in,
                              void* d_out, int out_size)
{
    const float* hs   = (const float*)d_in[0];
    const float* wqkv = (const float*)d_in[1];
    const float* bqkv = (const float*)d_in[2];
    const float* wo   = (const float*)d_in[3];
    const float* bo   = (const float*)d_in[4];
    const float* rope = (const float*)d_in[5];
    float* out = (float*)d_out;

    float *qkv, *att, *hsr, *wqT, *woT, *kfh, *kfl, *vfh, *vfl;
    cudaGetSymbolAddress((void**)&qkv, g_qkv);
    cudaGetSymbolAddress((void**)&att, g_att);
    cudaGetSymbolAddress((void**)&hsr, g_hsr);
    cudaGetSymbolAddress((void**)&wqT, g_wqT);
    cudaGetSymbolAddress((void**)&woT, g_woT);
    cudaGetSymbolAddress((void**)&kfh, g_kfh);
    cudaGetSymbolAddress((void**)&kfl, g_kfl);
    cudaGetSymbolAddress((void**)&vfh, g_vfh);
    cudaGetSymbolAddress((void**)&vfl, g_vfl);

    cudaFuncSetAttribute(gemm_tf32_cp,
                         cudaFuncAttributeMaxDynamicSharedMemorySize, GSMEM);
    cudaFuncSetAttribute(attn_mma,
                         cudaFuncAttributeMaxDynamicSharedMemorySize, ATTN_SMEM);

    // 0) Pre-pass: tf32-round hs; transpose+round weights to [N][K]
    round_tf32<<<(MROWS * KDIM) / 1024, 256>>>(hs, hsr, MROWS * KDIM);
    transpose_round<<<dim3(QKVW / 32, KDIM / 32), dim3(32, 8)>>>(wqkv, wqT, KDIM, QKVW);
    transpose_round<<<dim3(HID / 32, KDIM / 32), dim3(32, 8)>>>(wo, woT, KDIM, HID);

    // 1) QKV projection with FUSED RoPE epilogue
    gemm_tf32_cp<<<dim3(QKVW / 128, MROWS / 128), 256, GSMEM>>>(
        hsr, wqT, bqkv, qkv, QKVW, rope);

    // 2) Pre-split K/V into fragment-layout hi/lo tiles
    kv_frag_split<<<dim3(NTIL, NHB), 256>>>(qkv, kfh, kfl, vfh, vfl);

    // 3) Banded attention (3xTF32 mma, copy-only K/V staging)
    attn_mma<<<dim3(SEQ / QT, HEADS, BATCH), 256, ATTN_SMEM>>>(
        qkv, kfh, kfl, vfh, vfl, att);

    // 4) Output projection (no rope)
    gemm_tf32_cp<<<dim3(HID / 128, MROWS / 128), 256, GSMEM>>>(
        att, woT, bo, out, HID, nullptr);
}